// round 15
// baseline (speedup 1.0000x reference)
#include <cuda_runtime.h>
#include <cuda_fp16.h>
#include <math.h>

#define NN      50000
#define EE      1600000
#define FIN     256
#define H       4
#define D       32
#define HD      128
#define C       16

// ---------------- scratch ------------------------------------------------
__device__ __align__(16) __half g_feat1h[NN * HD];
__device__ __align__(16) float g_el1[NN * H];
__device__ __align__(16) float g_er1[NN * H];
__device__ __align__(16) float g_h[NN * HD];
__device__ __align__(16) __half g_feat2h[NN * C];
__device__ __align__(16) float g_el2[NN];
__device__ __align__(16) float g_er2[NN];
// CSR build (g_cnt zero-initialized at load; k_scan_all re-zeroes it each run)
__device__ int g_cnt[NN];
__device__ int g_off[NN + 1];
__device__ int g_cur[NN];
__device__ int g_ebuf[EE];

__device__ __forceinline__ float lrelu(float v) { return v > 0.f ? v : 0.2f * v; }
__device__ __forceinline__ float elu1(float v)  { return v > 0.f ? v : (__expf(v) - 1.f); }

__device__ __forceinline__ void mma_f16(float c[4], unsigned a0, unsigned a1,
                                        unsigned a2, unsigned a3,
                                        unsigned b0, unsigned b1) {
    asm volatile("mma.sync.aligned.m16n8k16.row.col.f32.f16.f16.f32 "
                 "{%0,%1,%2,%3}, {%4,%5,%6,%7}, {%8,%9}, {%0,%1,%2,%3};"
                 : "+f"(c[0]), "+f"(c[1]), "+f"(c[2]), "+f"(c[3])
                 : "r"(a0), "r"(a1), "r"(a2), "r"(a3), "r"(b0), "r"(b1));
}

__device__ __forceinline__ void split2(float2 v, unsigned& hi, unsigned& lo) {
    __half2 h = __floats2half2_rn(v.x, v.y);
    float2 hb = __half22float2(h);
    __half2 l = __floats2half2_rn(v.x - hb.x, v.y - hb.y);
    hi = *(unsigned*)&h;
    lo = *(unsigned*)&l;
}

// ---------------- CSR build ---------------------------------------------
__global__ void k_hist(const int* __restrict__ dst, int e_cnt) {
    int e = blockIdx.x * blockDim.x + threadIdx.x;
    if (e < e_cnt) atomicAdd(&g_cnt[dst[e]], 1);
}

// single-block full scan: 1024 threads x 49 contiguous nodes each.
// Also zeroes g_cnt for the next graph replay.
__global__ __launch_bounds__(1024) void k_scan_all(int e_cnt) {
    const int PER = 49;                     // 1024*49 = 50176 >= NN
    __shared__ int sh[1024];
    int t = threadIdx.x;
    int base = t * PER;
    int sum = 0;
#pragma unroll 7
    for (int i = 0; i < PER; i++) {
        int idx = base + i;
        if (idx < NN) sum += g_cnt[idx];
    }
    sh[t] = sum;
    __syncthreads();
#pragma unroll
    for (int ofs = 1; ofs < 1024; ofs <<= 1) {
        int v = (t >= ofs) ? sh[t - ofs] : 0;
        __syncthreads();
        sh[t] += v;
        __syncthreads();
    }
    int run = sh[t] - sum;
#pragma unroll 7
    for (int i = 0; i < PER; i++) {
        int idx = base + i;
        if (idx < NN) {
            int c = g_cnt[idx];
            g_off[idx] = run;
            g_cur[idx] = run;
            g_cnt[idx] = 0;                 // restore for next replay
            run += c;
        }
    }
    if (t == 0) g_off[NN] = e_cnt;
}

__global__ void k_scatter(const int* __restrict__ src, const int* __restrict__ dst, int e_cnt) {
    int e = blockIdx.x * blockDim.x + threadIdx.x;
    if (e >= e_cnt) return;
    int pos = atomicAdd(&g_cur[dst[e]], 1);
    g_ebuf[pos] = src[e];
}

// ---------------- K1: feat1 = x @ W1 via fp16 hi/lo HMMA ---------------
__global__ __launch_bounds__(256) void k_gemm1_tc(const float* __restrict__ x,
                                                  const float* __restrict__ W1,
                                                  const float* __restrict__ al1,
                                                  const float* __restrict__ ar1,
                                                  int n) {
    __shared__ float ws_raw[32][128];
    __shared__ uint4 wfrag[2][16][32];     // [k16][n8][lane]
    __shared__ float al_s[128], ar_s[128];
    int t = threadIdx.x;
    int lane = t & 31;
    int wid = t >> 5;
    int gid = lane >> 2;
    int tg = lane & 3;
    int warp_m = wid >> 1;
    int warp_n = wid & 1;
    int row0 = blockIdx.x * 128;
    if (t < 128) al_s[t] = al1[t];
    else         ar_s[t - 128] = ar1[t - 128];

    float acc[2][8][4];
#pragma unroll
    for (int m = 0; m < 2; m++)
#pragma unroll
        for (int j = 0; j < 8; j++) { acc[m][j][0]=0.f; acc[m][j][1]=0.f; acc[m][j][2]=0.f; acc[m][j][3]=0.f; }

    for (int kb = 0; kb < 8; kb++) {
        int K0 = kb * 32;
        unsigned Ahi[2][2][4], Alo[2][2][4];
#pragma unroll
        for (int m = 0; m < 2; m++) {
            int r = row0 + warp_m * 32 + m * 16 + gid;
            int rok0 = (r < n);
            int rok8 = (r + 8 < n);
            const float* xr0 = &x[(long)r * FIN + K0 + tg * 2];
            const float* xr8 = xr0 + 8L * FIN;
#pragma unroll
            for (int k16 = 0; k16 < 2; k16++) {
                float2 v0 = rok0 ? *(const float2*)&xr0[k16 * 16]     : make_float2(0.f, 0.f);
                float2 v1 = rok8 ? *(const float2*)&xr8[k16 * 16]     : make_float2(0.f, 0.f);
                float2 v2 = rok0 ? *(const float2*)&xr0[k16 * 16 + 8] : make_float2(0.f, 0.f);
                float2 v3 = rok8 ? *(const float2*)&xr8[k16 * 16 + 8] : make_float2(0.f, 0.f);
                split2(v0, Ahi[m][k16][0], Alo[m][k16][0]);
                split2(v1, Ahi[m][k16][1], Alo[m][k16][1]);
                split2(v2, Ahi[m][k16][2], Alo[m][k16][2]);
                split2(v3, Ahi[m][k16][3], Alo[m][k16][3]);
            }
        }
        __syncthreads();
#pragma unroll
        for (int i = 0; i < 4; i++) {
            int idx = t * 4 + i * 1024;
            int r = idx >> 7, c4 = idx & 127;
            *(float4*)&ws_raw[r][c4] = *(const float4*)&W1[(K0 + r) * HD + c4];
        }
        __syncthreads();
#pragma unroll
        for (int i = 0; i < 4; i++) {
            int e = t + i * 256;
            int k16 = e >> 9;
            int n8 = (e >> 5) & 15;
            int ln = e & 31;
            int eg = ln >> 2, et = ln & 3;
            int col = n8 * 8 + eg;
            int kr = k16 * 16 + et * 2;
            unsigned hi0, lo0, hi1, lo1;
            split2(make_float2(ws_raw[kr][col],     ws_raw[kr + 1][col]), hi0, lo0);
            split2(make_float2(ws_raw[kr + 8][col], ws_raw[kr + 9][col]), hi1, lo1);
            wfrag[k16][n8][ln] = make_uint4(hi0, hi1, lo0, lo1);
        }
        __syncthreads();
#pragma unroll
        for (int k16 = 0; k16 < 2; k16++) {
#pragma unroll
            for (int j = 0; j < 8; j++) {
                uint4 q = wfrag[k16][warp_n * 8 + j][lane];
#pragma unroll
                for (int m = 0; m < 2; m++) {
                    mma_f16(acc[m][j], Ahi[m][k16][0], Ahi[m][k16][1],
                            Ahi[m][k16][2], Ahi[m][k16][3], q.x, q.y);
                    mma_f16(acc[m][j], Ahi[m][k16][0], Ahi[m][k16][1],
                            Ahi[m][k16][2], Ahi[m][k16][3], q.z, q.w);
                    mma_f16(acc[m][j], Alo[m][k16][0], Alo[m][k16][1],
                            Alo[m][k16][2], Alo[m][k16][3], q.x, q.y);
                }
            }
        }
    }

#pragma unroll
    for (int m = 0; m < 2; m++) {
#pragma unroll
        for (int rv = 0; rv < 2; rv++) {
            int gr = row0 + warp_m * 32 + m * 16 + gid + rv * 8;
            int ci = rv * 2;
            float el0 = 0.f, er0 = 0.f, el1v = 0.f, er1v = 0.f;
#pragma unroll
            for (int j = 0; j < 8; j++) {
                int col = warp_n * 64 + j * 8 + tg * 2;
                float c0 = acc[m][j][ci], c1 = acc[m][j][ci + 1];
                float ep = c0 * al_s[col] + c1 * al_s[col + 1];
                float rp = c0 * ar_s[col] + c1 * ar_s[col + 1];
                if (j < 4) { el0 += ep; er0 += rp; }
                else       { el1v += ep; er1v += rp; }
            }
            el0 += __shfl_xor_sync(0xffffffffu, el0, 1);
            el0 += __shfl_xor_sync(0xffffffffu, el0, 2);
            er0 += __shfl_xor_sync(0xffffffffu, er0, 1);
            er0 += __shfl_xor_sync(0xffffffffu, er0, 2);
            el1v += __shfl_xor_sync(0xffffffffu, el1v, 1);
            el1v += __shfl_xor_sync(0xffffffffu, el1v, 2);
            er1v += __shfl_xor_sync(0xffffffffu, er1v, 1);
            er1v += __shfl_xor_sync(0xffffffffu, er1v, 2);
            if (gr < n) {
#pragma unroll
                for (int j = 0; j < 8; j++) {
                    int col = warp_n * 64 + j * 8 + tg * 2;
                    __half2 hv = __floats2half2_rn(acc[m][j][ci], acc[m][j][ci + 1]);
                    *(__half2*)&g_feat1h[(long)gr * HD + col] = hv;
                }
                if (tg == 0) {
                    int h0 = warp_n * 2;
                    g_el1[gr * 4 + h0] = el0;
                    g_el1[gr * 4 + h0 + 1] = el1v;
                    g_er1[gr * 4 + h0] = er0;
                    g_er1[gr * 4 + h0 + 1] = er1v;
                }
            }
        }
    }
}

// ---------------- K2: fused layer-1, edge loop unrolled x4 --------------
__global__ __launch_bounds__(256) void k_layer1(const float* __restrict__ b1, int n) {
    int wid = (blockIdx.x * blockDim.x + threadIdx.x) >> 5;
    if (wid >= n) return;
    int lane = threadIdx.x & 31;
    int head = lane >> 3;
    long fofs = lane * 4;
    int off0 = g_off[wid], off1 = g_off[wid + 1];
    float er = g_er1[wid * 4 + head];
    float ax = 0.f, ay = 0.f, az = 0.f, aw = 0.f, wsum = 0.f;

    int j = off0;
    for (; j + 4 <= off1; j += 4) {
        int s0 = __ldg(&g_ebuf[j]);
        int s1 = __ldg(&g_ebuf[j + 1]);
        int s2 = __ldg(&g_ebuf[j + 2]);
        int s3 = __ldg(&g_ebuf[j + 3]);
        float e0 = __ldg(&g_el1[s0 * 4 + head]);
        float e1 = __ldg(&g_el1[s1 * 4 + head]);
        float e2 = __ldg(&g_el1[s2 * 4 + head]);
        float e3 = __ldg(&g_el1[s3 * 4 + head]);
        uint2 p0 = *(const uint2*)&g_feat1h[(long)s0 * HD + fofs];
        uint2 p1 = *(const uint2*)&g_feat1h[(long)s1 * HD + fofs];
        uint2 p2 = *(const uint2*)&g_feat1h[(long)s2 * HD + fofs];
        uint2 p3 = *(const uint2*)&g_feat1h[(long)s3 * HD + fofs];
        float w0 = __expf(lrelu(e0 + er));
        float w1 = __expf(lrelu(e1 + er));
        float w2 = __expf(lrelu(e2 + er));
        float w3 = __expf(lrelu(e3 + er));
        wsum += (w0 + w1) + (w2 + w3);
        float2 a0 = __half22float2(*(__half2*)&p0.x), b0 = __half22float2(*(__half2*)&p0.y);
        float2 a1 = __half22float2(*(__half2*)&p1.x), b1v = __half22float2(*(__half2*)&p1.y);
        float2 a2 = __half22float2(*(__half2*)&p2.x), b2v = __half22float2(*(__half2*)&p2.y);
        float2 a3 = __half22float2(*(__half2*)&p3.x), b3v = __half22float2(*(__half2*)&p3.y);
        ax += a0.x * w0 + a1.x * w1 + a2.x * w2 + a3.x * w3;
        ay += a0.y * w0 + a1.y * w1 + a2.y * w2 + a3.y * w3;
        az += b0.x * w0 + b1v.x * w1 + b2v.x * w2 + b3v.x * w3;
        aw += b0.y * w0 + b1v.y * w1 + b2v.y * w2 + b3v.y * w3;
    }
    for (; j < off1; j++) {
        int s = __ldg(&g_ebuf[j]);
        float el = __ldg(&g_el1[s * 4 + head]);
        uint2 p = *(const uint2*)&g_feat1h[(long)s * HD + fofs];
        float w = __expf(lrelu(el + er));
        float2 f01 = __half22float2(*(__half2*)&p.x);
        float2 f23 = __half22float2(*(__half2*)&p.y);
        ax += f01.x * w; ay += f01.y * w; az += f23.x * w; aw += f23.y * w;
        wsum += w;
    }
    float inv = 1.f / fmaxf(wsum, 1e-9f);
    float4 b = *(const float4*)&b1[lane * 4];
    float4 o;
    o.x = elu1(ax * inv + b.x);
    o.y = elu1(ay * inv + b.y);
    o.z = elu1(az * inv + b.z);
    o.w = elu1(aw * inv + b.w);
    *(float4*)&g_h[(long)wid * HD + lane * 4] = o;
}

// ---------------- K3: feat2 = h @ W2 + el2/er2 --------------------------
__global__ __launch_bounds__(256) void k_gemm2(const float* __restrict__ W2,
                                               const float* __restrict__ al2,
                                               const float* __restrict__ ar2, int n) {
    __shared__ float w2s[HD * C];
    __shared__ float al2s[C], ar2s[C];
    int t = threadIdx.x;
    for (int j = t; j < HD * C; j += 256) w2s[j] = W2[j];
    if (t < C) { al2s[t] = al2[t]; ar2s[t] = ar2[t]; }
    __syncthreads();
    int node = blockIdx.x * 256 + t;
    if (node >= n) return;
    float acc[C];
#pragma unroll
    for (int c = 0; c < C; c++) acc[c] = 0.f;
    const float* hr = &g_h[(long)node * HD];
#pragma unroll 4
    for (int kk = 0; kk < 32; kk++) {
        float4 f = *(const float4*)&hr[kk * 4];
        const float* wrow = &w2s[(kk * 4) * C];
#pragma unroll
        for (int c = 0; c < C; c++) {
            acc[c] += f.x * wrow[c] + f.y * wrow[C + c] + f.z * wrow[2 * C + c] + f.w * wrow[3 * C + c];
        }
    }
    float el = 0.f, er = 0.f;
#pragma unroll
    for (int c = 0; c < C; c++) { el += acc[c] * al2s[c]; er += acc[c] * ar2s[c]; }
    __half* outp = &g_feat2h[(long)node * C];
#pragma unroll
    for (int c2 = 0; c2 < 8; c2++) {
        __half2 hv = __floats2half2_rn(acc[c2 * 2], acc[c2 * 2 + 1]);
        *(__half2*)&outp[c2 * 2] = hv;
    }
    g_el2[node] = el;
    g_er2[node] = er;
}

// ---------------- K4: fused layer-2, edge loop unrolled x4 --------------
__global__ __launch_bounds__(256) void k_layer2(const float* __restrict__ b2,
                                                float* __restrict__ out, int n) {
    int t = threadIdx.x;
    int d = blockIdx.x * 16 + (t >> 4);
    if (d >= n) return;
    int c = t & 15;
    int off0 = g_off[d], off1 = g_off[d + 1];
    float er = g_er2[d];
    float acc = 0.f, wsum = 0.f;

    int j = off0;
    for (; j + 4 <= off1; j += 4) {
        int s0 = __ldg(&g_ebuf[j]);
        int s1 = __ldg(&g_ebuf[j + 1]);
        int s2 = __ldg(&g_ebuf[j + 2]);
        int s3 = __ldg(&g_ebuf[j + 3]);
        float e0 = __ldg(&g_el2[s0]);
        float e1 = __ldg(&g_el2[s1]);
        float e2 = __ldg(&g_el2[s2]);
        float e3 = __ldg(&g_el2[s3]);
        float f0 = __half2float(g_feat2h[(long)s0 * C + c]);
        float f1 = __half2float(g_feat2h[(long)s1 * C + c]);
        float f2 = __half2float(g_feat2h[(long)s2 * C + c]);
        float f3 = __half2float(g_feat2h[(long)s3 * C + c]);
        float w0 = __expf(lrelu(e0 + er));
        float w1 = __expf(lrelu(e1 + er));
        float w2 = __expf(lrelu(e2 + er));
        float w3 = __expf(lrelu(e3 + er));
        acc += f0 * w0 + f1 * w1 + f2 * w2 + f3 * w3;
        wsum += (w0 + w1) + (w2 + w3);
    }
    for (; j < off1; j++) {
        int s = __ldg(&g_ebuf[j]);
        float el = __ldg(&g_el2[s]);
        float f = __half2float(g_feat2h[(long)s * C + c]);
        float w = __expf(lrelu(el + er));
        acc += f * w;
        wsum += w;
    }
    out[(long)d * C + c] = acc / fmaxf(wsum, 1e-9f) + __ldg(&b2[c]);
}

extern "C" void kernel_launch(void* const* d_in, const int* in_sizes, int n_in,
                              void* d_out, int out_size) {
    const float* x   = (const float*)d_in[0];
    const int*   src = (const int*)d_in[1];
    const int*   dst = (const int*)d_in[2];
    const float* W1  = (const float*)d_in[3];
    const float* b1  = (const float*)d_in[4];
    const float* al1 = (const float*)d_in[5];
    const float* ar1 = (const float*)d_in[6];
    const float* W2  = (const float*)d_in[7];
    const float* b2  = (const float*)d_in[8];
    const float* al2 = (const float*)d_in[9];
    const float* ar2 = (const float*)d_in[10];
    float* out = (float*)d_out;

    int n = in_sizes[0] / FIN;   // 50000
    int e = in_sizes[1];         // 1600000
    int eb = (e + 255) / 256;

    static cudaStream_t s_csr = nullptr;
    static cudaEvent_t ev_fork = nullptr, ev_join = nullptr;
    if (s_csr == nullptr) {
        cudaStreamCreateWithFlags(&s_csr, cudaStreamNonBlocking);
        cudaEventCreateWithFlags(&ev_fork, cudaEventDisableTiming);
        cudaEventCreateWithFlags(&ev_join, cudaEventDisableTiming);
    }

    // fork: CSR build on side stream, gemm1 on main stream
    cudaEventRecord(ev_fork, 0);
    cudaStreamWaitEvent(s_csr, ev_fork, 0);

    k_hist<<<eb, 256, 0, s_csr>>>(dst, e);
    k_scan_all<<<1, 1024, 0, s_csr>>>(e);
    k_scatter<<<eb, 256, 0, s_csr>>>(src, dst, e);
    cudaEventRecord(ev_join, s_csr);

    k_gemm1_tc<<<(n + 127) / 128, 256>>>(x, W1, al1, ar1, n);

    // join: layer1 needs both gemm1 (stream 0) and CSR (s_csr)
    cudaStreamWaitEvent(0, ev_join, 0);

    k_layer1<<<(n * 32 + 255) / 256, 256>>>(b1, n);
    k_gemm2<<<(n + 255) / 256, 256>>>(W2, al2, ar2, n);
    k_layer2<<<(n * 16 + 255) / 256, 256>>>(b2, out, n);
}